// round 14
// baseline (speedup 1.0000x reference)
#include <cuda_runtime.h>

#define NU 100000
#define NI 50000
#define NN 150000
#define NP 150016        // padded
#define NSB 147          // scan blocks of 1024 over NP
#define DIM 64
#define EE 3200000
#define BP 16384

#define HB (EE / 4 / 256)                 // hist blocks   = 3125
#define CB (NN * DIM / 4 / 256)           // concat blocks = 9375

#define GEMM_SMEM (2 * 64 * 68 * 4)       // Xs + Wt = 34816 bytes

// ---- device scratch (alloc-free) ----
__device__ float  g_dinv[NP];
__device__ float2 g_degcnt[NP];    // (weighted degree, count) — zero in .bss, re-zeroed each run
__device__ int    g_offs[NP + 1];
__device__ int    g_cur[NP];
__device__ int    g_bsum[NSB];
__device__ int2   g_csr[EE];       // (src, norm-as-bits)
__device__ float  g_H[NP * DIM];   // residual stream
__device__ float  g_HW[NP * DIM];  // h @ W

// -------- fused prologue: histogram (blocks < HB) + concat (rest) ------------
__global__ void k_pre(const int4* __restrict__ dst4, const float4* __restrict__ ew4,
                      const float4* __restrict__ U, const float4* __restrict__ I) {
    if (blockIdx.x < HB) {
        int i = blockIdx.x * blockDim.x + threadIdx.x;
        int4  d = dst4[i];
        float4 w = ew4[i];
#define HADD(DD, WW)                                                              \
        asm volatile("red.global.add.v2.f32 [%0], {%1, %2};"                      \
                     :: "l"(&g_degcnt[DD]), "f"(WW), "f"(1.0f) : "memory")
        HADD(d.x, w.x); HADD(d.y, w.y); HADD(d.z, w.z); HADD(d.w, w.w);
#undef HADD
    } else {
        int i = (blockIdx.x - HB) * blockDim.x + threadIdx.x;
        const int nu4 = NU * DIM / 4;
        float4 v = (i < nu4) ? U[i] : I[i - nu4];
        ((float4*)g_H)[i] = v;
    }
}

// ---------------- scan pass 1 (+ dinv fused; deg has implicit +1 self-loop) --
__device__ __forceinline__ int warp_incl_scan(int x, int lane) {
#pragma unroll
    for (int o = 1; o < 32; o <<= 1) {
        int y = __shfl_up_sync(0xffffffffu, x, o);
        if (lane >= o) x += y;
    }
    return x;
}

__global__ __launch_bounds__(256) void k_scan1() {
    __shared__ int wsum[8];
    int t = threadIdx.x, lane = t & 31, wid = t >> 5;
    int base = blockIdx.x * 1024 + t * 4;
    int v[4], s = 0;
#pragma unroll
    for (int j = 0; j < 4; j++) {
        int idx = base + j;
        if (idx < NP) {
            float2 dc = g_degcnt[idx];
            v[j] = (int)dc.y;
            g_dinv[idx] = rsqrtf(1.0f + dc.x);   // self-loop weight folded
        } else v[j] = 0;
        s += v[j];
    }
    int incl = warp_incl_scan(s, lane);
    if (lane == 31) wsum[wid] = incl;
    __syncthreads();
    if (t == 0) {
        int run = 0;
#pragma unroll
        for (int i = 0; i < 8; i++) { int tmp = wsum[i]; wsum[i] = run; run += tmp; }
    }
    __syncthreads();
    int excl = incl - s + wsum[wid];
    int run = excl;
#pragma unroll
    for (int j = 0; j < 4; j++) {
        if (base + j < NP) g_offs[base + j] = run;
        run += v[j];
    }
    if (t == 255) g_bsum[blockIdx.x] = excl + s;
}

// ---------------- scan pass 2: add block prefix; also reset degcnt -----------
__global__ __launch_bounds__(256) void k_scan3() {
    __shared__ int red[256];
    int t = threadIdx.x;
    int v = (t < NSB && t < blockIdx.x) ? g_bsum[t] : 0;
    red[t] = v;
    __syncthreads();
#pragma unroll
    for (int o = 128; o > 0; o >>= 1) {
        if (t < o) red[t] += red[t + o];
        __syncthreads();
    }
    int pref = red[0];
    int base = blockIdx.x * 1024;
#pragma unroll
    for (int j = 0; j < 4; j++) {
        int i = base + t + j * 256;
        if (i < NP) {
            int o = g_offs[i] + pref;
            g_offs[i] = o;
            g_cur[i] = o;
            g_degcnt[i] = make_float2(0.0f, 0.0f);   // clean for next run
        }
    }
    if (blockIdx.x == 0 && t == 0) g_offs[NP] = EE;
}

// ---------------- CSR build: packed (src, norm), 4 edges/thread --------------
__global__ void k_build(const int4* __restrict__ src4, const int4* __restrict__ dst4,
                        const float4* __restrict__ ew4) {
    int i = blockIdx.x * blockDim.x + threadIdx.x;
    if (i < EE / 4) {
        int4  s = src4[i];
        int4  d = dst4[i];
        float4 w = ew4[i];
        {
            float nw = g_dinv[s.x] * w.x * g_dinv[d.x];
            int pos = atomicAdd(&g_cur[d.x], 1);
            g_csr[pos] = make_int2(s.x, __float_as_int(nw));
        }
        {
            float nw = g_dinv[s.y] * w.y * g_dinv[d.y];
            int pos = atomicAdd(&g_cur[d.y], 1);
            g_csr[pos] = make_int2(s.y, __float_as_int(nw));
        }
        {
            float nw = g_dinv[s.z] * w.z * g_dinv[d.z];
            int pos = atomicAdd(&g_cur[d.z], 1);
            g_csr[pos] = make_int2(s.z, __float_as_int(nw));
        }
        {
            float nw = g_dinv[s.w] * w.w * g_dinv[d.w];
            int pos = atomicAdd(&g_cur[d.w], 1);
            g_csr[pos] = make_int2(s.w, __float_as_int(nw));
        }
    }
}

// ---------------- GEMM: HW = H @ W  (tensor cores, 3xTF32, R7 variant) -------
__device__ __forceinline__ void tf32_split(float v, unsigned& hi, unsigned& lo) {
    asm("cvt.rna.tf32.f32 %0, %1;" : "=r"(hi) : "f"(v));
    float rem = v - __uint_as_float(hi);
    asm("cvt.rna.tf32.f32 %0, %1;" : "=r"(lo) : "f"(rem));
}

#define MMA_TF32(C, A0, A1, A2, A3, B0, B1)                                         \
    asm("mma.sync.aligned.m16n8k8.row.col.f32.tf32.tf32.f32 "                       \
        "{%0,%1,%2,%3},{%4,%5,%6,%7},{%8,%9},{%0,%1,%2,%3};"                        \
        : "+f"(C[0]), "+f"(C[1]), "+f"(C[2]), "+f"(C[3])                            \
        : "r"(A0), "r"(A1), "r"(A2), "r"(A3), "r"(B0), "r"(B1))

__global__ __launch_bounds__(256) void k_gemm(const float* __restrict__ W) {
    extern __shared__ float sm[];
    float* Xs = sm;                 // 64 x 68
    float* Wt = sm + 64 * 68;       // transposed: Wt[n*68 + k]
    int tid = threadIdx.x;
    int row0 = blockIdx.x * 64;

    const float4* H4 = (const float4*)&g_H[row0 * 64];
#pragma unroll
    for (int i = 0; i < 4; i++) {
        int idx = tid + i * 256;       // 0..1023 float4s
        int row = idx >> 4, c4 = idx & 15;
        ((float4*)&Xs[row * 68])[c4] = H4[idx];
    }
    const float4* W4 = (const float4*)W;
#pragma unroll
    for (int i = 0; i < 4; i++) {
        int idx = tid + i * 256;       // 0..1023 float4s over 64x64 (k-major)
        int k = idx >> 4, c4 = idx & 15;
        float4 v = W4[idx];
        const float* vv = &v.x;
#pragma unroll
        for (int j = 0; j < 4; j++) {
            int n = c4 * 4 + j;
            Wt[n * 68 + k] = vv[j];
        }
    }
    __syncthreads();

    int warp = tid >> 5, lane = tid & 31;
    int gid = lane >> 2, tg = lane & 3;
    int mrow = (warp & 3) * 16;
    int ncol0 = (warp >> 2) * 32;

    float c[4][4];
#pragma unroll
    for (int nt = 0; nt < 4; nt++)
#pragma unroll
        for (int j = 0; j < 4; j++) c[nt][j] = 0.0f;

#pragma unroll
    for (int s = 0; s < 8; s++) {
        int kb = s * 8;
        float a0f = Xs[(mrow + gid) * 68 + kb + tg];
        float a1f = Xs[(mrow + gid + 8) * 68 + kb + tg];
        float a2f = Xs[(mrow + gid) * 68 + kb + tg + 4];
        float a3f = Xs[(mrow + gid + 8) * 68 + kb + tg + 4];
        unsigned ah0, al0, ah1, al1, ah2, al2, ah3, al3;
        tf32_split(a0f, ah0, al0);
        tf32_split(a1f, ah1, al1);
        tf32_split(a2f, ah2, al2);
        tf32_split(a3f, ah3, al3);
#pragma unroll
        for (int nt = 0; nt < 4; nt++) {
            int nb = ncol0 + nt * 8 + gid;
            float b0f = Wt[nb * 68 + kb + tg];
            float b1f = Wt[nb * 68 + kb + tg + 4];
            unsigned bh0, bl0, bh1, bl1;
            tf32_split(b0f, bh0, bl0);
            tf32_split(b1f, bh1, bl1);
            MMA_TF32(c[nt], ah0, ah1, ah2, ah3, bl0, bl1);   // hi * lo
            MMA_TF32(c[nt], al0, al1, al2, al3, bh0, bh1);   // lo * hi
            MMA_TF32(c[nt], ah0, ah1, ah2, ah3, bh0, bh1);   // hi * hi
        }
    }

    int rA = row0 + mrow + gid;
#pragma unroll
    for (int nt = 0; nt < 4; nt++) {
        int col = ncol0 + nt * 8 + tg * 2;
        *(float2*)&g_HW[rA * 64 + col]       = make_float2(c[nt][0], c[nt][1]);
        *(float2*)&g_HW[(rA + 8) * 64 + col] = make_float2(c[nt][2], c[nt][3]);
    }
}

// -------- fused conv gather + bias + LN + ReLU + residual (sw-pipelined) -----
__global__ __launch_bounds__(256) void k_conv_ln(const float* __restrict__ bias,
                                                 const float* __restrict__ gam,
                                                 const float* __restrict__ bet) {
    int gw = (blockIdx.x * blockDim.x + threadIdx.x) >> 5;
    int lane = threadIdx.x & 31;
    if (gw >= NN) return;
    int d = gw;
    int e0 = g_offs[d], e1 = g_offs[d + 1];
    const float2* __restrict__ HW2 = (const float2*)g_HW;
    float ax = 0.f, ay = 0.f;

    int eend4 = e0 + ((e1 - e0) & ~3);
    int e = e0;
    int2 c0, c1, c2, c3;
    if (e < eend4) {                        // prologue: prime the CSR pipeline
        c0 = __ldg(&g_csr[e]);
        c1 = __ldg(&g_csr[e + 1]);
        c2 = __ldg(&g_csr[e + 2]);
        c3 = __ldg(&g_csr[e + 3]);
    }
    while (e < eend4) {
        int en = e + 4;
        int2 n0, n1, n2, n3;
        if (en < eend4) {                   // prefetch next CSR group
            n0 = __ldg(&g_csr[en]);
            n1 = __ldg(&g_csr[en + 1]);
            n2 = __ldg(&g_csr[en + 2]);
            n3 = __ldg(&g_csr[en + 3]);
        }
        float2 v0 = HW2[c0.x * 32 + lane];
        float2 v1 = HW2[c1.x * 32 + lane];
        float2 v2 = HW2[c2.x * 32 + lane];
        float2 v3 = HW2[c3.x * 32 + lane];
        float w0 = __int_as_float(c0.y), w1 = __int_as_float(c1.y);
        float w2 = __int_as_float(c2.y), w3 = __int_as_float(c3.y);
        ax = fmaf(w0, v0.x, ax); ay = fmaf(w0, v0.y, ay);
        ax = fmaf(w1, v1.x, ax); ay = fmaf(w1, v1.y, ay);
        ax = fmaf(w2, v2.x, ax); ay = fmaf(w2, v2.y, ay);
        ax = fmaf(w3, v3.x, ax); ay = fmaf(w3, v3.y, ay);
        c0 = n0; c1 = n1; c2 = n2; c3 = n3;
        e = en;
    }
    for (; e < e1; e++) {                   // remainder (<4 edges)
        int2 c = __ldg(&g_csr[e]);
        float w = __int_as_float(c.y);
        float2 v = HW2[c.x * 32 + lane];
        ax = fmaf(w, v.x, ax); ay = fmaf(w, v.y, ay);
    }
    // self-loop + bias
    float di = g_dinv[d];
    float sn = di * di;
    float2 hv = HW2[d * 32 + lane];
    float2 b2 = ((const float2*)bias)[lane];
    ax = fmaf(sn, hv.x, ax) + b2.x;
    ay = fmaf(sn, hv.y, ay) + b2.y;
    // layernorm over 64 (2 per lane)
    float s = ax + ay;
#pragma unroll
    for (int o = 16; o > 0; o >>= 1) s += __shfl_xor_sync(0xffffffffu, s, o);
    float m = s * (1.0f / 64.0f);
    float d0 = ax - m, d1 = ay - m;
    float q = d0 * d0 + d1 * d1;
#pragma unroll
    for (int o = 16; o > 0; o >>= 1) q += __shfl_xor_sync(0xffffffffu, q, o);
    float rs = rsqrtf(q * (1.0f / 64.0f) + 1e-5f);
    float2 g2 = ((const float2*)gam)[lane];
    float2 be2 = ((const float2*)bet)[lane];
    float y0 = fmaxf(fmaf(d0 * rs, g2.x, be2.x), 0.0f);
    float y1 = fmaxf(fmaf(d1 * rs, g2.y, be2.y), 0.0f);
    float2* H2 = (float2*)g_H;
    float2 res = H2[d * 32 + lane];
    H2[d * 32 + lane] = make_float2(res.x + y0, res.y + y1);
}

// ---------------- fused projection + dot + bias + clip ----------------
__global__ __launch_bounds__(256) void k_score(const int* __restrict__ users,
                                               const int* __restrict__ items,
                                               const float* __restrict__ Wp,
                                               const float* __restrict__ bp,
                                               const float* __restrict__ bu,
                                               const float* __restrict__ bi,
                                               const float* __restrict__ mu,
                                               float* __restrict__ out) {
    __shared__ float Wps[64 * 64];
    __shared__ float bps[64];
    int tid = threadIdx.x;
    for (int i = tid; i < 64 * 64; i += 256) Wps[i] = Wp[i];
    if (tid < 64) bps[tid] = bp[tid];
    __syncthreads();
    int wid = tid >> 5, lane = tid & 31;
    int pair = blockIdx.x * 8 + wid;
    if (pair >= BP) return;
    int u = users[pair], it = items[pair];
    const float* hu = &g_H[u * 64];
    const float* hi = &g_H[(NU + it) * 64];
    float a0 = hu[lane], a1 = hu[lane + 32];
    float c0 = hi[lane], c1 = hi[lane + 32];
    float pu0 = bps[lane], pu1 = bps[lane + 32];
    float pi0 = bps[lane], pi1 = bps[lane + 32];
#pragma unroll
    for (int k = 0; k < 32; k++) {
        float ak = __shfl_sync(0xffffffffu, a0, k);
        float ck = __shfl_sync(0xffffffffu, c0, k);
        float w0 = Wps[k * 64 + lane], w1 = Wps[k * 64 + lane + 32];
        pu0 += ak * w0; pu1 += ak * w1;
        pi0 += ck * w0; pi1 += ck * w1;
    }
#pragma unroll
    for (int k = 0; k < 32; k++) {
        float ak = __shfl_sync(0xffffffffu, a1, k);
        float ck = __shfl_sync(0xffffffffu, c1, k);
        float w0 = Wps[(k + 32) * 64 + lane], w1 = Wps[(k + 32) * 64 + lane + 32];
        pu0 += ak * w0; pu1 += ak * w1;
        pi0 += ck * w0; pi1 += ck * w1;
    }
    float dt = pu0 * pi0 + pu1 * pi1;
#pragma unroll
    for (int o = 16; o > 0; o >>= 1) dt += __shfl_xor_sync(0xffffffffu, dt, o);
    if (lane == 0) {
        float sv = dt + bu[u] + bi[it] + mu[0];
        out[pair] = fminf(fmaxf(sv, 1.0f), 5.0f);
    }
}

extern "C" void kernel_launch(void* const* d_in, const int* in_sizes, int n_in,
                              void* d_out, int out_size) {
    (void)in_sizes; (void)n_in; (void)out_size;
    const int*   users = (const int*)d_in[0];
    const int*   items = (const int*)d_in[1];
    const int*   ei    = (const int*)d_in[2];
    const float* ew    = (const float*)d_in[3];
    const float* U     = (const float*)d_in[4];
    const float* I     = (const float*)d_in[5];
    const float* W0    = (const float*)d_in[6];
    const float* b0    = (const float*)d_in[7];
    const float* g0    = (const float*)d_in[8];
    const float* be0   = (const float*)d_in[9];
    const float* W1    = (const float*)d_in[10];
    const float* b1    = (const float*)d_in[11];
    const float* g1    = (const float*)d_in[12];
    const float* be1   = (const float*)d_in[13];
    const float* Wp    = (const float*)d_in[14];
    const float* bp    = (const float*)d_in[15];
    const float* bu    = (const float*)d_in[16];
    const float* bi    = (const float*)d_in[17];
    const float* mu    = (const float*)d_in[18];
    float* out = (float*)d_out;
    const int* src = ei;
    const int* dst = ei + EE;

    cudaFuncSetAttribute(k_gemm, cudaFuncAttributeMaxDynamicSharedMemorySize, GEMM_SMEM);

    // Launch index 3 (the ncu capture slot) is k_gemm (layer 0).
    k_pre<<<HB + CB, 256>>>((const int4*)dst, (const float4*)ew,
                            (const float4*)U, (const float4*)I);
    k_scan1<<<NSB, 256>>>();
    k_scan3<<<NSB, 256>>>();
    k_gemm<<<NP / 64, 256, GEMM_SMEM>>>(W0);        // profiled slot
    k_build<<<(EE / 4 + 255) / 256, 256>>>((const int4*)src, (const int4*)dst,
                                           (const float4*)ew);

    k_conv_ln<<<(NN + 7) / 8, 256>>>(b0, g0, be0);  // layer 0
    k_gemm<<<NP / 64, 256, GEMM_SMEM>>>(W1);        // layer 1
    k_conv_ln<<<(NN + 7) / 8, 256>>>(b1, g1, be1);

    k_score<<<BP / 8, 256>>>(users, items, Wp, bp, bu, bi, mu, out);
}

// round 15
// speedup vs baseline: 1.6030x; 1.6030x over previous
#include <cuda_runtime.h>

#define NU 100000
#define NI 50000
#define NN 150000
#define NP 150016        // padded
#define NSB 147          // scan blocks of 1024 over NP
#define DIM 64
#define EE 3200000
#define BP 16384

#define HB (EE / 4 / 256)                 // hist blocks = 3125

#define GEMM_SMEM (2 * 64 * 68 * 4)       // Xs + Wt = 34816 bytes

// ---- device scratch (alloc-free) ----
__device__ float  g_dinv[NP];
__device__ float2 g_degcnt[NP];    // zero in .bss, re-zeroed each run
__device__ int    g_offs[NP + 1];
__device__ int    g_cur[NP];
__device__ int    g_bsum[NSB];
__device__ int2   g_csr[EE];       // (src, norm-as-bits)
__device__ float  g_H[NP * DIM];   // residual stream (written by conv layer 0)
__device__ float  g_HW[NP * DIM];  // h @ W

// -------- prologue: histogram only (concat eliminated) -----------------------
__global__ void k_pre(const int4* __restrict__ dst4, const float4* __restrict__ ew4) {
    int i = blockIdx.x * blockDim.x + threadIdx.x;
    int4  d = dst4[i];
    float4 w = ew4[i];
#define HADD(DD, WW)                                                              \
    asm volatile("red.global.add.v2.f32 [%0], {%1, %2};"                          \
                 :: "l"(&g_degcnt[DD]), "f"(WW), "f"(1.0f) : "memory")
    HADD(d.x, w.x); HADD(d.y, w.y); HADD(d.z, w.z); HADD(d.w, w.w);
#undef HADD
}

// ---------------- scan pass 1 (+ dinv fused; deg has implicit +1 self-loop) --
__device__ __forceinline__ int warp_incl_scan(int x, int lane) {
#pragma unroll
    for (int o = 1; o < 32; o <<= 1) {
        int y = __shfl_up_sync(0xffffffffu, x, o);
        if (lane >= o) x += y;
    }
    return x;
}

__global__ __launch_bounds__(256) void k_scan1() {
    __shared__ int wsum[8];
    int t = threadIdx.x, lane = t & 31, wid = t >> 5;
    int base = blockIdx.x * 1024 + t * 4;
    int v[4], s = 0;
#pragma unroll
    for (int j = 0; j < 4; j++) {
        int idx = base + j;
        if (idx < NP) {
            float2 dc = g_degcnt[idx];
            v[j] = (int)dc.y;
            g_dinv[idx] = rsqrtf(1.0f + dc.x);   // self-loop weight folded
        } else v[j] = 0;
        s += v[j];
    }
    int incl = warp_incl_scan(s, lane);
    if (lane == 31) wsum[wid] = incl;
    __syncthreads();
    if (t == 0) {
        int run = 0;
#pragma unroll
        for (int i = 0; i < 8; i++) { int tmp = wsum[i]; wsum[i] = run; run += tmp; }
    }
    __syncthreads();
    int excl = incl - s + wsum[wid];
    int run = excl;
#pragma unroll
    for (int j = 0; j < 4; j++) {
        if (base + j < NP) g_offs[base + j] = run;
        run += v[j];
    }
    if (t == 255) g_bsum[blockIdx.x] = excl + s;
}

// ---------------- scan pass 2: add block prefix; also reset degcnt -----------
__global__ __launch_bounds__(256) void k_scan3() {
    __shared__ int red[256];
    int t = threadIdx.x;
    int v = (t < NSB && t < blockIdx.x) ? g_bsum[t] : 0;
    red[t] = v;
    __syncthreads();
#pragma unroll
    for (int o = 128; o > 0; o >>= 1) {
        if (t < o) red[t] += red[t + o];
        __syncthreads();
    }
    int pref = red[0];
    int base = blockIdx.x * 1024;
#pragma unroll
    for (int j = 0; j < 4; j++) {
        int i = base + t + j * 256;
        if (i < NP) {
            int o = g_offs[i] + pref;
            g_offs[i] = o;
            g_cur[i] = o;
            g_degcnt[i] = make_float2(0.0f, 0.0f);   // clean for next run
        }
    }
    if (blockIdx.x == 0 && t == 0) g_offs[NP] = EE;
}

// ---------------- CSR build: packed (src, norm), 4 edges/thread --------------
__global__ void k_build(const int4* __restrict__ src4, const int4* __restrict__ dst4,
                        const float4* __restrict__ ew4) {
    int i = blockIdx.x * blockDim.x + threadIdx.x;
    if (i < EE / 4) {
        int4  s = src4[i];
        int4  d = dst4[i];
        float4 w = ew4[i];
        {
            float nw = g_dinv[s.x] * w.x * g_dinv[d.x];
            int pos = atomicAdd(&g_cur[d.x], 1);
            g_csr[pos] = make_int2(s.x, __float_as_int(nw));
        }
        {
            float nw = g_dinv[s.y] * w.y * g_dinv[d.y];
            int pos = atomicAdd(&g_cur[d.y], 1);
            g_csr[pos] = make_int2(s.y, __float_as_int(nw));
        }
        {
            float nw = g_dinv[s.z] * w.z * g_dinv[d.z];
            int pos = atomicAdd(&g_cur[d.z], 1);
            g_csr[pos] = make_int2(s.z, __float_as_int(nw));
        }
        {
            float nw = g_dinv[s.w] * w.w * g_dinv[d.w];
            int pos = atomicAdd(&g_cur[d.w], 1);
            g_csr[pos] = make_int2(s.w, __float_as_int(nw));
        }
    }
}

// ---------------- GEMM: HW = X @ W  (tensor cores, 3xTF32, R7/R13 variant) ---
// layer0 != 0: X rows come from concat(U, I) directly (padding rows = 0).
__device__ __forceinline__ void tf32_split(float v, unsigned& hi, unsigned& lo) {
    asm("cvt.rna.tf32.f32 %0, %1;" : "=r"(hi) : "f"(v));
    float rem = v - __uint_as_float(hi);
    asm("cvt.rna.tf32.f32 %0, %1;" : "=r"(lo) : "f"(rem));
}

#define MMA_TF32(C, A0, A1, A2, A3, B0, B1)                                         \
    asm("mma.sync.aligned.m16n8k8.row.col.f32.tf32.tf32.f32 "                       \
        "{%0,%1,%2,%3},{%4,%5,%6,%7},{%8,%9},{%0,%1,%2,%3};"                        \
        : "+f"(C[0]), "+f"(C[1]), "+f"(C[2]), "+f"(C[3])                            \
        : "r"(A0), "r"(A1), "r"(A2), "r"(A3), "r"(B0), "r"(B1))

__global__ __launch_bounds__(256) void k_gemm(const float* __restrict__ W,
                                              const float4* __restrict__ U4,
                                              const float4* __restrict__ I4,
                                              int layer0) {
    extern __shared__ float sm[];
    float* Xs = sm;                 // 64 x 68
    float* Wt = sm + 64 * 68;       // transposed: Wt[n*68 + k]
    int tid = threadIdx.x;
    int row0 = blockIdx.x * 64;

    const int nu4 = NU * DIM / 4;
    const int nn4 = NN * DIM / 4;
    const float4* H4 = (const float4*)&g_H[row0 * 64];
#pragma unroll
    for (int i = 0; i < 4; i++) {
        int idx = tid + i * 256;       // 0..1023 float4s
        int row = idx >> 4, c4 = idx & 15;
        float4 v;
        if (layer0) {
            int g4 = row0 * 16 + idx;  // global float4 index into concat(U,I)
            if (g4 < nu4)      v = U4[g4];
            else if (g4 < nn4) v = I4[g4 - nu4];
            else               v = make_float4(0.f, 0.f, 0.f, 0.f);
        } else {
            v = H4[idx];
        }
        ((float4*)&Xs[row * 68])[c4] = v;
    }
    const float4* W4 = (const float4*)W;
#pragma unroll
    for (int i = 0; i < 4; i++) {
        int idx = tid + i * 256;       // 0..1023 float4s over 64x64 (k-major)
        int k = idx >> 4, c4 = idx & 15;
        float4 v = W4[idx];
        const float* vv = &v.x;
#pragma unroll
        for (int j = 0; j < 4; j++) {
            int n = c4 * 4 + j;
            Wt[n * 68 + k] = vv[j];
        }
    }
    __syncthreads();

    int warp = tid >> 5, lane = tid & 31;
    int gid = lane >> 2, tg = lane & 3;
    int mrow = (warp & 3) * 16;
    int ncol0 = (warp >> 2) * 32;

    float c[4][4];
#pragma unroll
    for (int nt = 0; nt < 4; nt++)
#pragma unroll
        for (int j = 0; j < 4; j++) c[nt][j] = 0.0f;

#pragma unroll
    for (int s = 0; s < 8; s++) {
        int kb = s * 8;
        float a0f = Xs[(mrow + gid) * 68 + kb + tg];
        float a1f = Xs[(mrow + gid + 8) * 68 + kb + tg];
        float a2f = Xs[(mrow + gid) * 68 + kb + tg + 4];
        float a3f = Xs[(mrow + gid + 8) * 68 + kb + tg + 4];
        unsigned ah0, al0, ah1, al1, ah2, al2, ah3, al3;
        tf32_split(a0f, ah0, al0);
        tf32_split(a1f, ah1, al1);
        tf32_split(a2f, ah2, al2);
        tf32_split(a3f, ah3, al3);
#pragma unroll
        for (int nt = 0; nt < 4; nt++) {
            int nb = ncol0 + nt * 8 + gid;
            float b0f = Wt[nb * 68 + kb + tg];
            float b1f = Wt[nb * 68 + kb + tg + 4];
            unsigned bh0, bl0, bh1, bl1;
            tf32_split(b0f, bh0, bl0);
            tf32_split(b1f, bh1, bl1);
            MMA_TF32(c[nt], ah0, ah1, ah2, ah3, bl0, bl1);   // hi * lo
            MMA_TF32(c[nt], al0, al1, al2, al3, bh0, bh1);   // lo * hi
            MMA_TF32(c[nt], ah0, ah1, ah2, ah3, bh0, bh1);   // hi * hi
        }
    }

    int rA = row0 + mrow + gid;
#pragma unroll
    for (int nt = 0; nt < 4; nt++) {
        int col = ncol0 + nt * 8 + tg * 2;
        *(float2*)&g_HW[rA * 64 + col]       = make_float2(c[nt][0], c[nt][1]);
        *(float2*)&g_HW[(rA + 8) * 64 + col] = make_float2(c[nt][2], c[nt][3]);
    }
}

// -------- fused conv gather + bias + LN + ReLU + residual (R13 loop) ---------
// layer0 != 0: residual read from U/I; g_H is write-only this pass.
__global__ __launch_bounds__(256) void k_conv_ln(const float* __restrict__ bias,
                                                 const float* __restrict__ gam,
                                                 const float* __restrict__ bet,
                                                 const float2* __restrict__ U2,
                                                 const float2* __restrict__ I2,
                                                 int layer0) {
    int gw = (blockIdx.x * blockDim.x + threadIdx.x) >> 5;
    int lane = threadIdx.x & 31;
    if (gw >= NN) return;
    int d = gw;
    int e0 = g_offs[d], e1 = g_offs[d + 1];
    const float2* __restrict__ HW2 = (const float2*)g_HW;
    float ax = 0.f, ay = 0.f;
    int e = e0;
    for (; e + 3 < e1; e += 4) {
        int2 c0 = __ldg(&g_csr[e]);
        int2 c1 = __ldg(&g_csr[e + 1]);
        int2 c2 = __ldg(&g_csr[e + 2]);
        int2 c3 = __ldg(&g_csr[e + 3]);
        float2 v0 = HW2[c0.x * 32 + lane];
        float2 v1 = HW2[c1.x * 32 + lane];
        float2 v2 = HW2[c2.x * 32 + lane];
        float2 v3 = HW2[c3.x * 32 + lane];
        float w0 = __int_as_float(c0.y), w1 = __int_as_float(c1.y);
        float w2 = __int_as_float(c2.y), w3 = __int_as_float(c3.y);
        ax = fmaf(w0, v0.x, ax); ay = fmaf(w0, v0.y, ay);
        ax = fmaf(w1, v1.x, ax); ay = fmaf(w1, v1.y, ay);
        ax = fmaf(w2, v2.x, ax); ay = fmaf(w2, v2.y, ay);
        ax = fmaf(w3, v3.x, ax); ay = fmaf(w3, v3.y, ay);
    }
    for (; e < e1; e++) {
        int2 c = __ldg(&g_csr[e]);
        float w = __int_as_float(c.y);
        float2 v = HW2[c.x * 32 + lane];
        ax = fmaf(w, v.x, ax); ay = fmaf(w, v.y, ay);
    }
    // self-loop + bias
    float di = g_dinv[d];
    float sn = di * di;
    float2 hv = HW2[d * 32 + lane];
    float2 b2 = ((const float2*)bias)[lane];
    ax = fmaf(sn, hv.x, ax) + b2.x;
    ay = fmaf(sn, hv.y, ay) + b2.y;
    // layernorm over 64 (2 per lane)
    float s = ax + ay;
#pragma unroll
    for (int o = 16; o > 0; o >>= 1) s += __shfl_xor_sync(0xffffffffu, s, o);
    float m = s * (1.0f / 64.0f);
    float d0 = ax - m, d1 = ay - m;
    float q = d0 * d0 + d1 * d1;
#pragma unroll
    for (int o = 16; o > 0; o >>= 1) q += __shfl_xor_sync(0xffffffffu, q, o);
    float rs = rsqrtf(q * (1.0f / 64.0f) + 1e-5f);
    float2 g2 = ((const float2*)gam)[lane];
    float2 be2 = ((const float2*)bet)[lane];
    float y0 = fmaxf(fmaf(d0 * rs, g2.x, be2.x), 0.0f);
    float y1 = fmaxf(fmaf(d1 * rs, g2.y, be2.y), 0.0f);
    float2 res;
    if (layer0) {
        res = (d < NU) ? U2[d * 32 + lane] : I2[(d - NU) * 32 + lane];
    } else {
        res = ((const float2*)g_H)[d * 32 + lane];
    }
    ((float2*)g_H)[d * 32 + lane] = make_float2(res.x + y0, res.y + y1);
}

// ---------------- fused projection + dot + bias + clip ----------------
__global__ __launch_bounds__(256) void k_score(const int* __restrict__ users,
                                               const int* __restrict__ items,
                                               const float* __restrict__ Wp,
                                               const float* __restrict__ bp,
                                               const float* __restrict__ bu,
                                               const float* __restrict__ bi,
                                               const float* __restrict__ mu,
                                               float* __restrict__ out) {
    __shared__ float Wps[64 * 64];
    __shared__ float bps[64];
    int tid = threadIdx.x;
    for (int i = tid; i < 64 * 64; i += 256) Wps[i] = Wp[i];
    if (tid < 64) bps[tid] = bp[tid];
    __syncthreads();
    int wid = tid >> 5, lane = tid & 31;
    int pair = blockIdx.x * 8 + wid;
    if (pair >= BP) return;
    int u = users[pair], it = items[pair];
    const float* hu = &g_H[u * 64];
    const float* hi = &g_H[(NU + it) * 64];
    float a0 = hu[lane], a1 = hu[lane + 32];
    float c0 = hi[lane], c1 = hi[lane + 32];
    float pu0 = bps[lane], pu1 = bps[lane + 32];
    float pi0 = bps[lane], pi1 = bps[lane + 32];
#pragma unroll
    for (int k = 0; k < 32; k++) {
        float ak = __shfl_sync(0xffffffffu, a0, k);
        float ck = __shfl_sync(0xffffffffu, c0, k);
        float w0 = Wps[k * 64 + lane], w1 = Wps[k * 64 + lane + 32];
        pu0 += ak * w0; pu1 += ak * w1;
        pi0 += ck * w0; pi1 += ck * w1;
    }
#pragma unroll
    for (int k = 0; k < 32; k++) {
        float ak = __shfl_sync(0xffffffffu, a1, k);
        float ck = __shfl_sync(0xffffffffu, c1, k);
        float w0 = Wps[(k + 32) * 64 + lane], w1 = Wps[(k + 32) * 64 + lane + 32];
        pu0 += ak * w0; pu1 += ak * w1;
        pi0 += ck * w0; pi1 += ck * w1;
    }
    float dt = pu0 * pi0 + pu1 * pi1;
#pragma unroll
    for (int o = 16; o > 0; o >>= 1) dt += __shfl_xor_sync(0xffffffffu, dt, o);
    if (lane == 0) {
        float sv = dt + bu[u] + bi[it] + mu[0];
        out[pair] = fminf(fmaxf(sv, 1.0f), 5.0f);
    }
}

extern "C" void kernel_launch(void* const* d_in, const int* in_sizes, int n_in,
                              void* d_out, int out_size) {
    (void)in_sizes; (void)n_in; (void)out_size;
    const int*   users = (const int*)d_in[0];
    const int*   items = (const int*)d_in[1];
    const int*   ei    = (const int*)d_in[2];
    const float* ew    = (const float*)d_in[3];
    const float* U     = (const float*)d_in[4];
    const float* I     = (const float*)d_in[5];
    const float* W0    = (const float*)d_in[6];
    const float* b0    = (const float*)d_in[7];
    const float* g0    = (const float*)d_in[8];
    const float* be0   = (const float*)d_in[9];
    const float* W1    = (const float*)d_in[10];
    const float* b1    = (const float*)d_in[11];
    const float* g1    = (const float*)d_in[12];
    const float* be1   = (const float*)d_in[13];
    const float* Wp    = (const float*)d_in[14];
    const float* bp    = (const float*)d_in[15];
    const float* bu    = (const float*)d_in[16];
    const float* bi    = (const float*)d_in[17];
    const float* mu    = (const float*)d_in[18];
    float* out = (float*)d_out;
    const int* src = ei;
    const int* dst = ei + EE;

    cudaFuncSetAttribute(k_gemm, cudaFuncAttributeMaxDynamicSharedMemorySize, GEMM_SMEM);

    // Launch index 3 (the ncu capture slot) is k_gemm (layer 0).
    k_pre<<<HB, 256>>>((const int4*)dst, (const float4*)ew);
    k_scan1<<<NSB, 256>>>();
    k_scan3<<<NSB, 256>>>();
    k_gemm<<<NP / 64, 256, GEMM_SMEM>>>(W0, (const float4*)U, (const float4*)I, 1);
    k_build<<<(EE / 4 + 255) / 256, 256>>>((const int4*)src, (const int4*)dst,
                                           (const float4*)ew);

    k_conv_ln<<<(NN + 7) / 8, 256>>>(b0, g0, be0,
                                     (const float2*)U, (const float2*)I, 1);
    k_gemm<<<NP / 64, 256, GEMM_SMEM>>>(W1, (const float4*)U, (const float4*)I, 0);
    k_conv_ln<<<(NN + 7) / 8, 256>>>(b1, g1, be1,
                                     (const float2*)U, (const float2*)I, 0);

    k_score<<<BP / 8, 256>>>(users, items, Wp, bp, bu, bi, mu, out);
}

// round 16
// speedup vs baseline: 1.6293x; 1.0164x over previous
#include <cuda_runtime.h>

#define NU 100000
#define NI 50000
#define NN 150000
#define NP 150016        // padded
#define NSB 147          // scan blocks of 1024 over NP
#define DIM 64
#define EE 3200000
#define BP 16384

#define HB (EE / 4 / 256)                 // hist blocks = 3125

#define GEMM_SMEM (2 * 64 * 68 * 4)       // Xs + Wt = 34816 bytes

// ---- device scratch (alloc-free) ----
__device__ float  g_dinv[NP];
__device__ float2 g_degcnt[NP];    // zero in .bss, re-zeroed each run
__device__ int    g_offs[NP + 1];
__device__ int    g_cur[NP];
__device__ int    g_bsum[NSB];
__device__ int2   g_csr[EE];       // (src, norm-as-bits)
__device__ float  g_H[NP * DIM];   // residual stream (written by conv layer 0)
__device__ float  g_HW[NP * DIM];  // h @ W

// -------- prologue: histogram only -------------------------------------------
__global__ void k_pre(const int4* __restrict__ dst4, const float4* __restrict__ ew4) {
    int i = blockIdx.x * blockDim.x + threadIdx.x;
    int4  d = dst4[i];
    float4 w = ew4[i];
#define HADD(DD, WW)                                                              \
    asm volatile("red.global.add.v2.f32 [%0], {%1, %2};"                          \
                 :: "l"(&g_degcnt[DD]), "f"(WW), "f"(1.0f) : "memory")
    HADD(d.x, w.x); HADD(d.y, w.y); HADD(d.z, w.z); HADD(d.w, w.w);
#undef HADD
}

// ---------------- scan pass 1 (+ dinv fused; deg has implicit +1 self-loop) --
__device__ __forceinline__ int warp_incl_scan(int x, int lane) {
#pragma unroll
    for (int o = 1; o < 32; o <<= 1) {
        int y = __shfl_up_sync(0xffffffffu, x, o);
        if (lane >= o) x += y;
    }
    return x;
}

__global__ __launch_bounds__(256) void k_scan1() {
    __shared__ int wsum[8];
    int t = threadIdx.x, lane = t & 31, wid = t >> 5;
    int base = blockIdx.x * 1024 + t * 4;
    int v[4], s = 0;
#pragma unroll
    for (int j = 0; j < 4; j++) {
        int idx = base + j;
        if (idx < NP) {
            float2 dc = g_degcnt[idx];
            v[j] = (int)dc.y;
            g_dinv[idx] = rsqrtf(1.0f + dc.x);   // self-loop weight folded
        } else v[j] = 0;
        s += v[j];
    }
    int incl = warp_incl_scan(s, lane);
    if (lane == 31) wsum[wid] = incl;
    __syncthreads();
    if (t == 0) {
        int run = 0;
#pragma unroll
        for (int i = 0; i < 8; i++) { int tmp = wsum[i]; wsum[i] = run; run += tmp; }
    }
    __syncthreads();
    int excl = incl - s + wsum[wid];
    int run = excl;
#pragma unroll
    for (int j = 0; j < 4; j++) {
        if (base + j < NP) g_offs[base + j] = run;
        run += v[j];
    }
    if (t == 255) g_bsum[blockIdx.x] = excl + s;
}

// ---------------- scan pass 2: add block prefix; also reset degcnt -----------
__global__ __launch_bounds__(256) void k_scan3() {
    __shared__ int red[256];
    int t = threadIdx.x;
    int v = (t < NSB && t < blockIdx.x) ? g_bsum[t] : 0;
    red[t] = v;
    __syncthreads();
#pragma unroll
    for (int o = 128; o > 0; o >>= 1) {
        if (t < o) red[t] += red[t + o];
        __syncthreads();
    }
    int pref = red[0];
    int base = blockIdx.x * 1024;
#pragma unroll
    for (int j = 0; j < 4; j++) {
        int i = base + t + j * 256;
        if (i < NP) {
            int o = g_offs[i] + pref;
            g_offs[i] = o;
            g_cur[i] = o;
            g_degcnt[i] = make_float2(0.0f, 0.0f);   // clean for next run
        }
    }
    if (blockIdx.x == 0 && t == 0) g_offs[NP] = EE;
}

// ---------------- CSR build: packed (src, norm), 4 edges/thread --------------
__global__ void k_build(const int4* __restrict__ src4, const int4* __restrict__ dst4,
                        const float4* __restrict__ ew4) {
    int i = blockIdx.x * blockDim.x + threadIdx.x;
    if (i < EE / 4) {
        int4  s = src4[i];
        int4  d = dst4[i];
        float4 w = ew4[i];
        {
            float nw = g_dinv[s.x] * w.x * g_dinv[d.x];
            int pos = atomicAdd(&g_cur[d.x], 1);
            g_csr[pos] = make_int2(s.x, __float_as_int(nw));
        }
        {
            float nw = g_dinv[s.y] * w.y * g_dinv[d.y];
            int pos = atomicAdd(&g_cur[d.y], 1);
            g_csr[pos] = make_int2(s.y, __float_as_int(nw));
        }
        {
            float nw = g_dinv[s.z] * w.z * g_dinv[d.z];
            int pos = atomicAdd(&g_cur[d.z], 1);
            g_csr[pos] = make_int2(s.z, __float_as_int(nw));
        }
        {
            float nw = g_dinv[s.w] * w.w * g_dinv[d.w];
            int pos = atomicAdd(&g_cur[d.w], 1);
            g_csr[pos] = make_int2(s.w, __float_as_int(nw));
        }
    }
}

// ---------------- GEMM: HW = X @ W  (tensor cores, 3xTF32) -------------------
__device__ __forceinline__ void tf32_split(float v, unsigned& hi, unsigned& lo) {
    asm("cvt.rna.tf32.f32 %0, %1;" : "=r"(hi) : "f"(v));
    float rem = v - __uint_as_float(hi);
    asm("cvt.rna.tf32.f32 %0, %1;" : "=r"(lo) : "f"(rem));
}

#define MMA_TF32(C, A0, A1, A2, A3, B0, B1)                                         \
    asm("mma.sync.aligned.m16n8k8.row.col.f32.tf32.tf32.f32 "                       \
        "{%0,%1,%2,%3},{%4,%5,%6,%7},{%8,%9},{%0,%1,%2,%3};"                        \
        : "+f"(C[0]), "+f"(C[1]), "+f"(C[2]), "+f"(C[3])                            \
        : "r"(A0), "r"(A1), "r"(A2), "r"(A3), "r"(B0), "r"(B1))

__global__ __launch_bounds__(256) void k_gemm(const float* __restrict__ W,
                                              const float4* __restrict__ U4,
                                              const float4* __restrict__ I4,
                                              int layer0) {
    extern __shared__ float sm[];
    float* Xs = sm;                 // 64 x 68
    float* Wt = sm + 64 * 68;       // transposed: Wt[n*68 + k]
    int tid = threadIdx.x;
    int row0 = blockIdx.x * 64;

    const int nu4 = NU * DIM / 4;
    const int nn4 = NN * DIM / 4;
    const float4* H4 = (const float4*)&g_H[row0 * 64];
#pragma unroll
    for (int i = 0; i < 4; i++) {
        int idx = tid + i * 256;       // 0..1023 float4s
        int row = idx >> 4, c4 = idx & 15;
        float4 v;
        if (layer0) {
            int g4 = row0 * 16 + idx;  // global float4 index into concat(U,I)
            if (g4 < nu4)      v = U4[g4];
            else if (g4 < nn4) v = I4[g4 - nu4];
            else               v = make_float4(0.f, 0.f, 0.f, 0.f);
        } else {
            v = H4[idx];
        }
        ((float4*)&Xs[row * 68])[c4] = v;
    }
    const float4* W4 = (const float4*)W;
#pragma unroll
    for (int i = 0; i < 4; i++) {
        int idx = tid + i * 256;       // 0..1023 float4s over 64x64 (k-major)
        int k = idx >> 4, c4 = idx & 15;
        float4 v = W4[idx];
        const float* vv = &v.x;
#pragma unroll
        for (int j = 0; j < 4; j++) {
            int n = c4 * 4 + j;
            Wt[n * 68 + k] = vv[j];
        }
    }
    __syncthreads();

    int warp = tid >> 5, lane = tid & 31;
    int gid = lane >> 2, tg = lane & 3;
    int mrow = (warp & 3) * 16;
    int ncol0 = (warp >> 2) * 32;

    float c[4][4];
#pragma unroll
    for (int nt = 0; nt < 4; nt++)
#pragma unroll
        for (int j = 0; j < 4; j++) c[nt][j] = 0.0f;

#pragma unroll
    for (int s = 0; s < 8; s++) {
        int kb = s * 8;
        float a0f = Xs[(mrow + gid) * 68 + kb + tg];
        float a1f = Xs[(mrow + gid + 8) * 68 + kb + tg];
        float a2f = Xs[(mrow + gid) * 68 + kb + tg + 4];
        float a3f = Xs[(mrow + gid + 8) * 68 + kb + tg + 4];
        unsigned ah0, al0, ah1, al1, ah2, al2, ah3, al3;
        tf32_split(a0f, ah0, al0);
        tf32_split(a1f, ah1, al1);
        tf32_split(a2f, ah2, al2);
        tf32_split(a3f, ah3, al3);
#pragma unroll
        for (int nt = 0; nt < 4; nt++) {
            int nb = ncol0 + nt * 8 + gid;
            float b0f = Wt[nb * 68 + kb + tg];
            float b1f = Wt[nb * 68 + kb + tg + 4];
            unsigned bh0, bl0, bh1, bl1;
            tf32_split(b0f, bh0, bl0);
            tf32_split(b1f, bh1, bl1);
            MMA_TF32(c[nt], ah0, ah1, ah2, ah3, bl0, bl1);   // hi * lo
            MMA_TF32(c[nt], al0, al1, al2, al3, bh0, bh1);   // lo * hi
            MMA_TF32(c[nt], ah0, ah1, ah2, ah3, bh0, bh1);   // hi * hi
        }
    }

    int rA = row0 + mrow + gid;
#pragma unroll
    for (int nt = 0; nt < 4; nt++) {
        int col = ncol0 + nt * 8 + tg * 2;
        *(float2*)&g_HW[rA * 64 + col]       = make_float2(c[nt][0], c[nt][1]);
        *(float2*)&g_HW[(rA + 8) * 64 + col] = make_float2(c[nt][2], c[nt][3]);
    }
}

// -------- fused conv gather + bias + LN + ReLU + residual --------------------
__global__ __launch_bounds__(256) void k_conv_ln(const float* __restrict__ bias,
                                                 const float* __restrict__ gam,
                                                 const float* __restrict__ bet,
                                                 const float2* __restrict__ U2,
                                                 const float2* __restrict__ I2,
                                                 int layer0) {
    int gw = (blockIdx.x * blockDim.x + threadIdx.x) >> 5;
    int lane = threadIdx.x & 31;
    if (gw >= NN) return;
    int d = gw;
    int e0 = g_offs[d], e1 = g_offs[d + 1];
    const float2* __restrict__ HW2 = (const float2*)g_HW;
    float ax = 0.f, ay = 0.f;
    int e = e0;
    for (; e + 3 < e1; e += 4) {
        int2 c0 = __ldg(&g_csr[e]);
        int2 c1 = __ldg(&g_csr[e + 1]);
        int2 c2 = __ldg(&g_csr[e + 2]);
        int2 c3 = __ldg(&g_csr[e + 3]);
        float2 v0 = HW2[c0.x * 32 + lane];
        float2 v1 = HW2[c1.x * 32 + lane];
        float2 v2 = HW2[c2.x * 32 + lane];
        float2 v3 = HW2[c3.x * 32 + lane];
        float w0 = __int_as_float(c0.y), w1 = __int_as_float(c1.y);
        float w2 = __int_as_float(c2.y), w3 = __int_as_float(c3.y);
        ax = fmaf(w0, v0.x, ax); ay = fmaf(w0, v0.y, ay);
        ax = fmaf(w1, v1.x, ax); ay = fmaf(w1, v1.y, ay);
        ax = fmaf(w2, v2.x, ax); ay = fmaf(w2, v2.y, ay);
        ax = fmaf(w3, v3.x, ax); ay = fmaf(w3, v3.y, ay);
    }
    for (; e < e1; e++) {
        int2 c = __ldg(&g_csr[e]);
        float w = __int_as_float(c.y);
        float2 v = HW2[c.x * 32 + lane];
        ax = fmaf(w, v.x, ax); ay = fmaf(w, v.y, ay);
    }
    // self-loop + bias
    float di = g_dinv[d];
    float sn = di * di;
    float2 hv = HW2[d * 32 + lane];
    float2 b2 = ((const float2*)bias)[lane];
    ax = fmaf(sn, hv.x, ax) + b2.x;
    ay = fmaf(sn, hv.y, ay) + b2.y;
    // layernorm over 64 (2 per lane)
    float s = ax + ay;
#pragma unroll
    for (int o = 16; o > 0; o >>= 1) s += __shfl_xor_sync(0xffffffffu, s, o);
    float m = s * (1.0f / 64.0f);
    float d0 = ax - m, d1 = ay - m;
    float q = d0 * d0 + d1 * d1;
#pragma unroll
    for (int o = 16; o > 0; o >>= 1) q += __shfl_xor_sync(0xffffffffu, q, o);
    float rs = rsqrtf(q * (1.0f / 64.0f) + 1e-5f);
    float2 g2 = ((const float2*)gam)[lane];
    float2 be2 = ((const float2*)bet)[lane];
    float y0 = fmaxf(fmaf(d0 * rs, g2.x, be2.x), 0.0f);
    float y1 = fmaxf(fmaf(d1 * rs, g2.y, be2.y), 0.0f);
    float2 res;
    if (layer0) {
        res = (d < NU) ? U2[d * 32 + lane] : I2[(d - NU) * 32 + lane];
    } else {
        res = ((const float2*)g_H)[d * 32 + lane];
    }
    ((float2*)g_H)[d * 32 + lane] = make_float2(res.x + y0, res.y + y1);
}

// ---------------- fused projection + dot + bias + clip ----------------
__global__ __launch_bounds__(256) void k_score(const int* __restrict__ users,
                                               const int* __restrict__ items,
                                               const float* __restrict__ Wp,
                                               const float* __restrict__ bp,
                                               const float* __restrict__ bu,
                                               const float* __restrict__ bi,
                                               const float* __restrict__ mu,
                                               float* __restrict__ out) {
    __shared__ float Wps[64 * 64];
    __shared__ float bps[64];
    int tid = threadIdx.x;
    for (int i = tid; i < 64 * 64; i += 256) Wps[i] = Wp[i];
    if (tid < 64) bps[tid] = bp[tid];
    __syncthreads();
    int wid = tid >> 5, lane = tid & 31;
    int pair = blockIdx.x * 8 + wid;
    if (pair >= BP) return;
    int u = users[pair], it = items[pair];
    const float* hu = &g_H[u * 64];
    const float* hi = &g_H[(NU + it) * 64];
    float a0 = hu[lane], a1 = hu[lane + 32];
    float c0 = hi[lane], c1 = hi[lane + 32];
    float pu0 = bps[lane], pu1 = bps[lane + 32];
    float pi0 = bps[lane], pi1 = bps[lane + 32];
#pragma unroll
    for (int k = 0; k < 32; k++) {
        float ak = __shfl_sync(0xffffffffu, a0, k);
        float ck = __shfl_sync(0xffffffffu, c0, k);
        float w0 = Wps[k * 64 + lane], w1 = Wps[k * 64 + lane + 32];
        pu0 += ak * w0; pu1 += ak * w1;
        pi0 += ck * w0; pi1 += ck * w1;
    }
#pragma unroll
    for (int k = 0; k < 32; k++) {
        float ak = __shfl_sync(0xffffffffu, a1, k);
        float ck = __shfl_sync(0xffffffffu, c1, k);
        float w0 = Wps[(k + 32) * 64 + lane], w1 = Wps[(k + 32) * 64 + lane + 32];
        pu0 += ak * w0; pu1 += ak * w1;
        pi0 += ck * w0; pi1 += ck * w1;
    }
    float dt = pu0 * pi0 + pu1 * pi1;
#pragma unroll
    for (int o = 16; o > 0; o >>= 1) dt += __shfl_xor_sync(0xffffffffu, dt, o);
    if (lane == 0) {
        float sv = dt + bu[u] + bi[it] + mu[0];
        out[pair] = fminf(fmaxf(sv, 1.0f), 5.0f);
    }
}

extern "C" void kernel_launch(void* const* d_in, const int* in_sizes, int n_in,
                              void* d_out, int out_size) {
    (void)in_sizes; (void)n_in; (void)out_size;
    const int*   users = (const int*)d_in[0];
    const int*   items = (const int*)d_in[1];
    const int*   ei    = (const int*)d_in[2];
    const float* ew    = (const float*)d_in[3];
    const float* U     = (const float*)d_in[4];
    const float* I     = (const float*)d_in[5];
    const float* W0    = (const float*)d_in[6];
    const float* b0    = (const float*)d_in[7];
    const float* g0    = (const float*)d_in[8];
    const float* be0   = (const float*)d_in[9];
    const float* W1    = (const float*)d_in[10];
    const float* b1    = (const float*)d_in[11];
    const float* g1    = (const float*)d_in[12];
    const float* be1   = (const float*)d_in[13];
    const float* Wp    = (const float*)d_in[14];
    const float* bp    = (const float*)d_in[15];
    const float* bu    = (const float*)d_in[16];
    const float* bi    = (const float*)d_in[17];
    const float* mu    = (const float*)d_in[18];
    float* out = (float*)d_out;
    const int* src = ei;
    const int* dst = ei + EE;

    // One-time host-side setup (no device allocation).
    static cudaStream_t s2 = nullptr;
    static cudaEvent_t evFork = nullptr, evG0 = nullptr;
    if (s2 == nullptr) {
        cudaStreamCreateWithFlags(&s2, cudaStreamNonBlocking);
        cudaEventCreateWithFlags(&evFork, cudaEventDisableTiming);
        cudaEventCreateWithFlags(&evG0, cudaEventDisableTiming);
        cudaFuncSetAttribute(k_gemm, cudaFuncAttributeMaxDynamicSharedMemorySize,
                             GEMM_SMEM);
    }

    // Fork: gemm0 (independent of the CSR chain) runs on s2 concurrently.
    cudaEventRecord(evFork, 0);
    cudaStreamWaitEvent(s2, evFork, 0);
    k_gemm<<<NP / 64, 256, GEMM_SMEM, s2>>>(W0, (const float4*)U, (const float4*)I, 1);
    cudaEventRecord(evG0, s2);

    // CSR chain on the main stream.
    k_pre<<<HB, 256>>>((const int4*)dst, (const float4*)ew);
    k_scan1<<<NSB, 256>>>();
    k_scan3<<<NSB, 256>>>();
    k_build<<<(EE / 4 + 255) / 256, 256>>>((const int4*)src, (const int4*)dst,
                                           (const float4*)ew);

    // Join: conv0 needs both the CSR and gemm0's HW.
    cudaStreamWaitEvent(0, evG0, 0);
    k_conv_ln<<<(NN + 7) / 8, 256>>>(b0, g0, be0,
                                     (const float2*)U, (const float2*)I, 1);
    k_gemm<<<NP / 64, 256, GEMM_SMEM>>>(W1, (const float4*)U, (const float4*)I, 0);
    k_conv_ln<<<(NN + 7) / 8, 256>>>(b1, g1, be1,
                                     (const float2*)U, (const float2*)I, 0);

    k_score<<<BP / 8, 256>>>(users, items, Wp, bp, bu, bi, mu, out);
}